// round 2
// baseline (speedup 1.0000x reference)
#include <cuda_runtime.h>

#define DI 1024
#define D2 2048
#define BB 32
#define SS 128
#define KK 512
#define NSTEP 12

// ---------------- device scratch (static, no cudaMalloc) ----------------
__device__ float g_qpa[NSTEP * BB * DI];     // q_pa_all [s][b][d]
__device__ float g_cq2[NSTEP * BB * DI];     // question-half of cq (+cq_b) [s][b][i]
__device__ float g_riwT[D2 * DI];            // ri_w transposed: riwT[j'][i] = ri_w[i][j']
__device__ float g_control[BB * DI];
__device__ float g_mem[BB * DI];
__device__ float g_v[BB * DI];               // new_control * ra_w
__device__ float g_read[BB * DI];
__device__ float g_clog[BB * SS];
__device__ float g_rlog[BB * KK];
__device__ float g_partA[8 * BB * D2];       // split-K partials (cq / u / new_memory)
__device__ float g_partB[4 * BB * DI];       // split-K partials (mem_p)

// ---------------- generic split-K GEMM: part[z][n][m] = sum_{k in chunk z} A[m,k]*act[n,k]
struct GTask {
    const float* A; int lda;
    const float* act0; int ld0; int split; const float* act1; int ld1;
    int M; int Kz;        // Kz = K per z-chunk
    float* part;
};

__global__ void __launch_bounds__(128) gemm_part(GTask ta, GTask tb) {
    GTask t = (blockIdx.y == 0) ? ta : tb;
    int z = blockIdx.z;
    int m0 = blockIdx.x * 32;
    if (m0 >= t.M) return;
    __shared__ float As[32][33];
    __shared__ float Bs[32][33];
    int tid = threadIdx.x;
    int n2 = tid & 15;   // n = 2*n2 + c
    int m4 = tid >> 4;   // m = 4*m4 + r
    float acc[4][2] = {};
    int kbase = z * t.Kz;
    for (int k0 = 0; k0 < t.Kz; k0 += 32) {
        int kg0 = kbase + k0;
#pragma unroll
        for (int i = 0; i < 8; i++) {
            int idx = tid + 128 * i;
            int mm = idx >> 5, kk = idx & 31;
            As[kk][mm] = t.A[(size_t)(m0 + mm) * t.lda + kg0 + kk];
            int kg = kg0 + kk;
            Bs[kk][mm] = (kg < t.split) ? t.act0[(size_t)mm * t.ld0 + kg]
                                        : t.act1[(size_t)mm * t.ld1 + (kg - t.split)];
        }
        __syncthreads();
#pragma unroll
        for (int kk = 0; kk < 32; kk++) {
            float b0 = Bs[kk][2 * n2], b1 = Bs[kk][2 * n2 + 1];
#pragma unroll
            for (int r = 0; r < 4; r++) {
                float a = As[kk][4 * m4 + r];
                acc[r][0] += a * b0;
                acc[r][1] += a * b1;
            }
        }
        __syncthreads();
    }
#pragma unroll
    for (int r = 0; r < 4; r++) {
        int m = m0 + 4 * m4 + r;
#pragma unroll
        for (int c = 0; c < 2; c++) {
            int n = 2 * n2 + c;
            t.part[(size_t)(z * BB + n) * t.M + m] = acc[r][c];
        }
    }
}

// ---------------- full GEMM with epilogue (precompute only) ----------------
// mode 0: out[n*M + m] = acc + bias[m]
// mode 1: m -> (s = m>>10, d = m&1023); out[(s*BB+n)*DI+d] = acc+bias; if s==0 also mem0
__global__ void __launch_bounds__(128) gemm_full(
    const float* __restrict__ A, int lda,
    const float* __restrict__ act, int ldact,
    int M, int K, float* __restrict__ out,
    const float* __restrict__ bias, int mode, float* __restrict__ mem0) {
    int m0 = blockIdx.x * 32;
    int n0 = blockIdx.y * 32;
    __shared__ float As[32][33];
    __shared__ float Bs[32][33];
    int tid = threadIdx.x;
    int n2 = tid & 15, m4 = tid >> 4;
    float acc[4][2] = {};
    for (int k0 = 0; k0 < K; k0 += 32) {
#pragma unroll
        for (int i = 0; i < 8; i++) {
            int idx = tid + 128 * i;
            int mm = idx >> 5, kk = idx & 31;
            As[kk][mm] = A[(size_t)(m0 + mm) * lda + k0 + kk];
            Bs[kk][mm] = act[(size_t)(n0 + mm) * ldact + k0 + kk];
        }
        __syncthreads();
#pragma unroll
        for (int kk = 0; kk < 32; kk++) {
            float b0 = Bs[kk][2 * n2], b1 = Bs[kk][2 * n2 + 1];
#pragma unroll
            for (int r = 0; r < 4; r++) {
                float a = As[kk][4 * m4 + r];
                acc[r][0] += a * b0;
                acc[r][1] += a * b1;
            }
        }
        __syncthreads();
    }
#pragma unroll
    for (int r = 0; r < 4; r++) {
        int m = m0 + 4 * m4 + r;
        float bs = bias[m];
#pragma unroll
        for (int c = 0; c < 2; c++) {
            int n = n0 + 2 * n2 + c;
            float vv = acc[r][c] + bs;
            if (mode == 0) {
                out[(size_t)n * M + m] = vv;
            } else {
                int s = m >> 10, d = m & 1023;
                out[(size_t)(s * BB + n) * DI + d] = vv;
                if (s == 0) mem0[(size_t)n * DI + d] = vv;
            }
        }
    }
}

// ---------------- transpose ri_w [DI x D2] -> riwT [D2 x DI] ----------------
__global__ void __launch_bounds__(256) transpose_riw(const float* __restrict__ ri_w) {
    __shared__ float tile[32][33];
    int j0 = blockIdx.x * 32;   // j' in [0,2048)
    int i0 = blockIdx.y * 32;   // i  in [0,1024)
    int tx = threadIdx.x & 31, ty = threadIdx.x >> 5;  // ty 0..7
#pragma unroll
    for (int r = 0; r < 32; r += 8)
        tile[ty + r][tx] = ri_w[(size_t)(i0 + ty + r) * D2 + j0 + tx];
    __syncthreads();
#pragma unroll
    for (int r = 0; r < 32; r += 8)
        g_riwT[(size_t)(j0 + ty + r) * DI + i0 + tx] = tile[tx][ty + r];
}

// ---------------- control init: broadcast scalar ----------------
__global__ void init_control(const float* __restrict__ cinit) {
    int i = blockIdx.x * 256 + threadIdx.x;
    if (i < BB * DI) g_control[i] = cinit[0];
}

// ---------------- context attention: logits ----------------
__global__ void __launch_bounds__(256) ctx_logits(const float* __restrict__ ctx,
                                                  const float* __restrict__ caw,
                                                  const float* __restrict__ cq2s) {
    int b = blockIdx.x;
    int sc = blockIdx.y;  // 0..3 -> 32 s-rows each
    __shared__ float w[DI];
    int tid = threadIdx.x;
    for (int d = tid; d < DI; d += 256) {
        float v = cq2s[(size_t)b * DI + d];
#pragma unroll
        for (int z = 0; z < 4; z++) v += g_partA[(size_t)(z * BB + b) * DI + d];
        w[d] = v * caw[d];
    }
    __syncthreads();
    int warp = tid >> 5, lane = tid & 31;
#pragma unroll
    for (int si = 0; si < 4; si++) {
        int srow = sc * 32 + warp * 4 + si;
        const float* crow = ctx + (size_t)(b * SS + srow) * DI;
        float acc = 0.f;
#pragma unroll 8
        for (int d = lane; d < DI; d += 32) acc += crow[d] * w[d];
#pragma unroll
        for (int o = 16; o; o >>= 1) acc += __shfl_xor_sync(0xffffffffu, acc, o);
        if (lane == 0) g_clog[b * SS + srow] = acc;
    }
}

// ---------------- context attention: softmax + weighted sum -> control, v ----------------
__global__ void __launch_bounds__(256) ctx_attend(const float* __restrict__ ctx,
                                                  const float* __restrict__ raw) {
    int b = blockIdx.x, dc = blockIdx.y, tid = threadIdx.x;
    __shared__ float p[SS];
    __shared__ float tmp[SS];
    if (tid < SS) { p[tid] = g_clog[b * SS + tid]; tmp[tid] = p[tid]; }
    __syncthreads();
    for (int st = 64; st >= 1; st >>= 1) {
        if (tid < st) tmp[tid] = fmaxf(tmp[tid], tmp[tid + st]);
        __syncthreads();
    }
    float mx = tmp[0];
    __syncthreads();
    if (tid < SS) { float e = expf(p[tid] - mx); p[tid] = e; tmp[tid] = e; }
    __syncthreads();
    for (int st = 64; st >= 1; st >>= 1) {
        if (tid < st) tmp[tid] += tmp[tid + st];
        __syncthreads();
    }
    float inv = 1.0f / tmp[0];
    int d = dc * 256 + tid;
    const float* base = ctx + (size_t)b * SS * DI + d;
    float acc = 0.f;
#pragma unroll 8
    for (int s2 = 0; s2 < SS; s2++) acc += p[s2] * base[(size_t)s2 * DI];
    acc *= inv;
    g_control[b * DI + d] = acc;
    g_v[b * DI + d] = acc * raw[d];
}

// ---------------- knowledge attention: logits ----------------
// w2[j] = (sum_z memp_part + rm_b[j]) * u1[j] + u2[j];  rlog[b,k] = sum_j w2[j]*kn[b,j,k]
__global__ void __launch_bounds__(256) know_logits(const float* __restrict__ kn,
                                                   const float* __restrict__ rmb) {
    int b = blockIdx.x, kc = blockIdx.y;  // kc 0..3 -> 128 k each
    int tid = threadIdx.x;
    __shared__ float w2[DI];
    __shared__ float partial[128];
    for (int j = tid; j < DI; j += 256) {
        float mp = rmb[j];
        float u1 = 0.f, u2 = 0.f;
#pragma unroll
        for (int z = 0; z < 4; z++) {
            mp += g_partB[(size_t)(z * BB + b) * DI + j];
            u1 += g_partA[(size_t)(z * BB + b) * D2 + j];
            u2 += g_partA[(size_t)(z * BB + b) * D2 + DI + j];
        }
        w2[j] = mp * u1 + u2;
    }
    __syncthreads();
    int k = kc * 128 + (tid & 127);
    int jh = tid >> 7;  // 0 or 1: which half of j-range
    const float* base = kn + (size_t)b * DI * KK + (size_t)jh * 512 * KK + k;
    const float* w2h = w2 + jh * 512;
    float acc = 0.f;
#pragma unroll 16
    for (int j = 0; j < 512; j++) acc += w2h[j] * base[(size_t)j * KK];
    if (jh) partial[tid & 127] = acc;
    __syncthreads();
    if (!jh) g_rlog[b * KK + k] = acc + partial[tid];
}

// ---------------- knowledge attention: softmax + read ----------------
__global__ void __launch_bounds__(256) know_attend(const float* __restrict__ kn) {
    int b = blockIdx.x, ic = blockIdx.y;  // ic 0..7 -> 128 i each
    int tid = threadIdx.x;
    __shared__ float p[KK];
    __shared__ float tmp[256];
    float l0 = g_rlog[b * KK + tid];
    float l1 = g_rlog[b * KK + 256 + tid];
    tmp[tid] = fmaxf(l0, l1);
    __syncthreads();
    for (int st = 128; st >= 1; st >>= 1) {
        if (tid < st) tmp[tid] = fmaxf(tmp[tid], tmp[tid + st]);
        __syncthreads();
    }
    float mx = tmp[0];
    __syncthreads();
    float e0 = expf(l0 - mx), e1 = expf(l1 - mx);
    p[tid] = e0;
    p[tid + 256] = e1;
    tmp[tid] = e0 + e1;
    __syncthreads();
    for (int st = 128; st >= 1; st >>= 1) {
        if (tid < st) tmp[tid] += tmp[tid + st];
        __syncthreads();
    }
    float inv = 1.0f / tmp[0];
    int warp = tid >> 5, lane = tid & 31;
#pragma unroll
    for (int ii = 0; ii < 16; ii++) {
        int i = ic * 128 + warp * 16 + ii;
        const float* row = kn + (size_t)(b * DI + i) * KK;
        float acc = 0.f;
#pragma unroll
        for (int t = 0; t < 16; t++) acc += p[lane + 32 * t] * row[lane + 32 * t];
#pragma unroll
        for (int o = 16; o; o >>= 1) acc += __shfl_xor_sync(0xffffffffu, acc, o);
        if (lane == 0) g_read[b * DI + i] = acc * inv;
    }
}

// ---------------- reduce new_memory partials + bias ----------------
__global__ void reduce_mem(const float* __restrict__ wmb, float* __restrict__ dst,
                           float* __restrict__ dst2, int nz) {
    int i = blockIdx.x * 256 + threadIdx.x;  // 0..32767
    int n = i >> 10, m = i & 1023;
    float v = wmb[m];
    for (int z = 0; z < nz; z++) v += g_partA[(size_t)(z * BB + n) * DI + m];
    dst[i] = v;
    if (dst2) dst2[i] = v;
}

// ---------------- host orchestration ----------------
extern "C" void kernel_launch(void* const* d_in, const int* in_sizes, int n_in,
                              void* d_out, int out_size) {
    const float* ctx      = (const float*)d_in[0];
    const float* question = (const float*)d_in[1];
    const float* kn       = (const float*)d_in[2];
    const float* cinit    = (const float*)d_in[3];
    const float* pa_w     = (const float*)d_in[4];
    const float* pa_b     = (const float*)d_in[5];
    const float* cq_w     = (const float*)d_in[6];
    const float* cq_b     = (const float*)d_in[7];
    const float* ca_w     = (const float*)d_in[8];
    const float* rm_w     = (const float*)d_in[10];
    const float* rm_b     = (const float*)d_in[11];
    const float* ri_w     = (const float*)d_in[12];
    const float* ra_w     = (const float*)d_in[14];
    const float* wm_w     = (const float*)d_in[16];
    const float* wm_b     = (const float*)d_in[17];
    float* out = (float*)d_out;

    void* p;
    cudaGetSymbolAddress(&p, g_qpa);     float* qpa   = (float*)p;
    cudaGetSymbolAddress(&p, g_cq2);     float* cq2   = (float*)p;
    cudaGetSymbolAddress(&p, g_riwT);    float* riwT  = (float*)p;
    cudaGetSymbolAddress(&p, g_control); float* ctrl  = (float*)p;
    cudaGetSymbolAddress(&p, g_mem);     float* memb  = (float*)p;
    cudaGetSymbolAddress(&p, g_v);       float* vbuf  = (float*)p;
    cudaGetSymbolAddress(&p, g_read);    float* readb = (float*)p;
    cudaGetSymbolAddress(&p, g_partA);   float* partA = (float*)p;
    cudaGetSymbolAddress(&p, g_partB);   float* partB = (float*)p;

    // ---- precompute ----
    transpose_riw<<<dim3(64, 32), 256>>>(ri_w);
    // q_pa_all: [12288 x 32] = pa_w[12288 x 2048] @ question[32 x 2048]^T (+pa_b)
    gemm_full<<<dim3(NSTEP * DI / 32, 1), 128>>>(pa_w, D2, question, D2,
                                                 NSTEP * DI, D2, qpa, pa_b, 1, memb);
    // cq2[s,b,i] = qpa[s,b,:] @ cq_w[:, D:]^T + cq_b   (N = 12*32 = 384)
    gemm_full<<<dim3(DI / 32, NSTEP * BB / 32), 128>>>(cq_w + DI, D2, qpa, DI,
                                                       DI, DI, cq2, cq_b, 0, nullptr);
    init_control<<<BB * DI / 256, 256>>>(cinit);

    // ---- 12 recurrent steps ----
    for (int s = 0; s < NSTEP; s++) {
        // (a) cq control-half -> partA[z<4][n][1024] ; (b) mem_p -> partB[z<4][n][1024]
        GTask ta = { cq_w, D2, ctrl, DI, D2, ctrl, DI, DI, 256, partA };
        GTask tb = { rm_w, DI, memb, DI, D2, memb, DI, DI, 256, partB };
        gemm_part<<<dim3(32, 2, 4), 128>>>(ta, tb);

        ctx_logits<<<dim3(BB, 4), 256>>>(ctx, ca_w, cq2 + (size_t)s * BB * DI);
        ctx_attend<<<dim3(BB, 4), 256>>>(ctx, ra_w);

        // (c) u[b,j'] = v[b,:] @ riwT[j',:]  -> partA[z<4][n][2048]
        GTask tc = { riwT, DI, vbuf, DI, D2, vbuf, DI, D2, 256, partA };
        gemm_part<<<dim3(64, 1, 4), 128>>>(tc, tc);

        know_logits<<<dim3(BB, 4), 256>>>(kn, rm_b);
        know_attend<<<dim3(BB, 8), 256>>>(kn);

        // (d) new_memory = concat(read, memory) @ wm_w^T -> partA[z<8][n][1024]
        GTask td = { wm_w, D2, readb, DI, DI, memb, DI, DI, 256, partA };
        gemm_part<<<dim3(32, 1, 8), 128>>>(td, td);

        reduce_mem<<<BB * DI / 256, 256>>>(wm_b, memb,
                                           (s == NSTEP - 1) ? out : nullptr, 8);
    }
}

// round 3
// speedup vs baseline: 2.0898x; 2.0898x over previous
#include <cuda_runtime.h>

#define DI 1024
#define D2 2048
#define BB 32
#define SS 128
#define KK 512
#define NSTEP 12

// ---------------- static device scratch ----------------
__device__ float g_qpa[NSTEP * BB * DI];
__device__ float g_cq2[NSTEP * BB * DI];
__device__ float g_riwT[D2 * DI];
__device__ float g_control[BB * DI];
__device__ float g_mem[BB * DI];
__device__ float g_v[BB * DI];
__device__ float g_read[BB * DI];
__device__ float g_clog[BB * SS];
__device__ float g_rlogp[4 * BB * KK];
__device__ float g_partA[8 * BB * D2];
__device__ float g_partB[4 * BB * DI];

// ---------------- skinny split-K GEMM: part[z][n][m] = sum_{k in chunk z} A[m,k]*act[n,k]
struct GTask {
    const float* A; int lda;
    const float* act0; const float* act1; int split; int ldact;
    int M; int kchunk;
    float* part;
};

__global__ void __launch_bounds__(256) sgemm_part(GTask ta, GTask tb) {
    GTask t = (blockIdx.y == 0) ? ta : tb;
    const int z = blockIdx.z;
    const int m0 = blockIdx.x * 64;
    __shared__ float As[64][65];
    __shared__ float Bs[64][36];
    const int tid = threadIdx.x;
    const int tm = tid & 31;
    const int n0 = (tid >> 5) * 4;
    float acc[2][4] = {};
    const int kbase = z * t.kchunk;
    const float* act = (kbase < t.split) ? t.act0 : t.act1;
    const int koff = (kbase < t.split) ? kbase : (kbase - t.split);
    for (int ks = 0; ks < t.kchunk; ks += 64) {
#pragma unroll
        for (int i = 0; i < 4; i++) {
            int idx = tid + 256 * i;
            int kg = idx & 15, m = idx >> 4;
            float4 av = *(const float4*)(t.A + (size_t)(m0 + m) * t.lda + kbase + ks + kg * 4);
            As[m][kg * 4 + 0] = av.x; As[m][kg * 4 + 1] = av.y;
            As[m][kg * 4 + 2] = av.z; As[m][kg * 4 + 3] = av.w;
        }
#pragma unroll
        for (int i = 0; i < 2; i++) {
            int idx = tid + 256 * i;
            int kg = idx & 15, n = idx >> 4;
            float4 bv = *(const float4*)(act + (size_t)n * t.ldact + koff + ks + kg * 4);
            Bs[kg * 4 + 0][n] = bv.x; Bs[kg * 4 + 1][n] = bv.y;
            Bs[kg * 4 + 2][n] = bv.z; Bs[kg * 4 + 3][n] = bv.w;
        }
        __syncthreads();
#pragma unroll
        for (int k = 0; k < 64; k++) {
            float4 bv = *(const float4*)&Bs[k][n0];
            float a0 = As[tm][k], a1 = As[tm + 32][k];
            acc[0][0] += a0 * bv.x; acc[0][1] += a0 * bv.y;
            acc[0][2] += a0 * bv.z; acc[0][3] += a0 * bv.w;
            acc[1][0] += a1 * bv.x; acc[1][1] += a1 * bv.y;
            acc[1][2] += a1 * bv.z; acc[1][3] += a1 * bv.w;
        }
        __syncthreads();
    }
#pragma unroll
    for (int r = 0; r < 2; r++) {
        int m = m0 + tm + 32 * r;
#pragma unroll
        for (int c = 0; c < 4; c++)
            t.part[(size_t)(z * BB + n0 + c) * t.M + m] = acc[r][c];
    }
}

// ---------------- full-K GEMM with epilogue (precompute) ----------------
// mode 0: out[n*M + m] = acc + bias[m]
// mode 1: m -> (s,d); out[(s*BB+n)*DI+d]; s==0 also writes mem0
__global__ void __launch_bounds__(256) sgemm_full(
    const float* __restrict__ A, int lda,
    const float* __restrict__ act, int ldact,
    int M, int K, float* __restrict__ out,
    const float* __restrict__ bias, int mode, float* __restrict__ mem0) {
    const int m0 = blockIdx.x * 64;
    const int n0g = blockIdx.y * 32;
    __shared__ float As[64][65];
    __shared__ float Bs[64][36];
    const int tid = threadIdx.x;
    const int tm = tid & 31;
    const int n0 = (tid >> 5) * 4;
    float acc[2][4] = {};
    for (int ks = 0; ks < K; ks += 64) {
#pragma unroll
        for (int i = 0; i < 4; i++) {
            int idx = tid + 256 * i;
            int kg = idx & 15, m = idx >> 4;
            float4 av = *(const float4*)(A + (size_t)(m0 + m) * lda + ks + kg * 4);
            As[m][kg * 4 + 0] = av.x; As[m][kg * 4 + 1] = av.y;
            As[m][kg * 4 + 2] = av.z; As[m][kg * 4 + 3] = av.w;
        }
#pragma unroll
        for (int i = 0; i < 2; i++) {
            int idx = tid + 256 * i;
            int kg = idx & 15, n = idx >> 4;
            float4 bv = *(const float4*)(act + (size_t)(n0g + n) * ldact + ks + kg * 4);
            Bs[kg * 4 + 0][n] = bv.x; Bs[kg * 4 + 1][n] = bv.y;
            Bs[kg * 4 + 2][n] = bv.z; Bs[kg * 4 + 3][n] = bv.w;
        }
        __syncthreads();
#pragma unroll
        for (int k = 0; k < 64; k++) {
            float4 bv = *(const float4*)&Bs[k][n0];
            float a0 = As[tm][k], a1 = As[tm + 32][k];
            acc[0][0] += a0 * bv.x; acc[0][1] += a0 * bv.y;
            acc[0][2] += a0 * bv.z; acc[0][3] += a0 * bv.w;
            acc[1][0] += a1 * bv.x; acc[1][1] += a1 * bv.y;
            acc[1][2] += a1 * bv.z; acc[1][3] += a1 * bv.w;
        }
        __syncthreads();
    }
#pragma unroll
    for (int r = 0; r < 2; r++) {
        int m = m0 + tm + 32 * r;
        float bs = bias[m];
#pragma unroll
        for (int c = 0; c < 4; c++) {
            int n = n0g + n0 + c;
            float vv = acc[r][c] + bs;
            if (mode == 0) {
                out[(size_t)n * M + m] = vv;
            } else {
                int s = m >> 10, d = m & 1023;
                out[(size_t)(s * BB + n) * DI + d] = vv;
                if (s == 0) mem0[(size_t)n * DI + d] = vv;
            }
        }
    }
}

// ---------------- transpose ri_w [DI x D2] -> riwT [D2 x DI] ----------------
__global__ void __launch_bounds__(256) transpose_riw(const float* __restrict__ ri_w) {
    __shared__ float tile[32][33];
    int j0 = blockIdx.x * 32;
    int i0 = blockIdx.y * 32;
    int tx = threadIdx.x & 31, ty = threadIdx.x >> 5;
#pragma unroll
    for (int r = 0; r < 32; r += 8)
        tile[ty + r][tx] = ri_w[(size_t)(i0 + ty + r) * D2 + j0 + tx];
    __syncthreads();
#pragma unroll
    for (int r = 0; r < 32; r += 8)
        g_riwT[(size_t)(j0 + ty + r) * DI + i0 + tx] = tile[tx][ty + r];
}

__global__ void init_control(const float* __restrict__ cinit) {
    int i = blockIdx.x * 256 + threadIdx.x;
    if (i < BB * DI) g_control[i] = cinit[0];
}

// ---------------- context attention: logits ----------------
__global__ void __launch_bounds__(256) ctx_logits(const float* __restrict__ ctx,
                                                  const float* __restrict__ caw,
                                                  const float* __restrict__ cq2s) {
    int b = blockIdx.x;
    int sc = blockIdx.y;  // 0..3
    __shared__ float w[DI];
    int tid = threadIdx.x;
    for (int d = tid; d < DI; d += 256) {
        float v = cq2s[(size_t)b * DI + d];
#pragma unroll
        for (int z = 0; z < 4; z++) v += g_partA[(size_t)(z * BB + b) * DI + d];
        w[d] = v * caw[d];
    }
    __syncthreads();
    int warp = tid >> 5, lane = tid & 31;
    const float4* w4 = (const float4*)w;
#pragma unroll
    for (int si = 0; si < 4; si++) {
        int srow = sc * 32 + warp * 4 + si;
        const float4* crow = (const float4*)(ctx + (size_t)(b * SS + srow) * DI);
        float acc = 0.f;
#pragma unroll
        for (int t = 0; t < 8; t++) {
            float4 f = crow[lane + 32 * t];
            float4 g = w4[lane + 32 * t];
            acc += f.x * g.x + f.y * g.y + f.z * g.z + f.w * g.w;
        }
#pragma unroll
        for (int o = 16; o; o >>= 1) acc += __shfl_xor_sync(0xffffffffu, acc, o);
        if (lane == 0) g_clog[b * SS + srow] = acc;
    }
}

// ---------------- context attention: softmax + weighted sum -> control, v ----------------
__global__ void __launch_bounds__(256) ctx_attend(const float* __restrict__ ctx,
                                                  const float* __restrict__ raw) {
    int b = blockIdx.x, dc = blockIdx.y, tid = threadIdx.x;
    __shared__ float p[SS];
    __shared__ float tmp[SS];
    if (tid < SS) { p[tid] = g_clog[b * SS + tid]; tmp[tid] = p[tid]; }
    __syncthreads();
    for (int st = 64; st >= 1; st >>= 1) {
        if (tid < st) tmp[tid] = fmaxf(tmp[tid], tmp[tid + st]);
        __syncthreads();
    }
    float mx = tmp[0];
    __syncthreads();
    if (tid < SS) { float e = expf(p[tid] - mx); p[tid] = e; tmp[tid] = e; }
    __syncthreads();
    for (int st = 64; st >= 1; st >>= 1) {
        if (tid < st) tmp[tid] += tmp[tid + st];
        __syncthreads();
    }
    float inv = 1.0f / tmp[0];
    int d = dc * 256 + tid;
    const float* base = ctx + (size_t)b * SS * DI + d;
    float acc = 0.f;
#pragma unroll 16
    for (int s2 = 0; s2 < SS; s2++) acc += p[s2] * base[(size_t)s2 * DI];
    acc *= inv;
    g_control[b * DI + d] = acc;
    g_v[b * DI + d] = acc * raw[d];
}

// ---------------- knowledge logits (partial over j) ----------------
__global__ void __launch_bounds__(256) know_logits_part(const float* __restrict__ kn,
                                                        const float* __restrict__ rmb) {
    const int b = blockIdx.x, kc = blockIdx.y, jc = blockIdx.z;
    const int tid = threadIdx.x;
    __shared__ float w2[256];
    __shared__ float half[128];
    {
        int j = jc * 256 + tid;
        float mp = rmb[j], u1 = 0.f, u2 = 0.f;
#pragma unroll
        for (int z = 0; z < 4; z++) {
            mp += g_partB[(size_t)(z * BB + b) * DI + j];
            u1 += g_partA[(size_t)(z * BB + b) * D2 + j];
            u2 += g_partA[(size_t)(z * BB + b) * D2 + DI + j];
        }
        w2[tid] = mp * u1 + u2;
    }
    __syncthreads();
    const int k = kc * 128 + (tid & 127);
    const int jh = tid >> 7;
    const float* base = kn + (size_t)b * DI * KK + (size_t)(jc * 256 + jh * 128) * KK + k;
    const float* ww = w2 + jh * 128;
    float acc = 0.f;
#pragma unroll 8
    for (int j = 0; j < 128; j++) acc += ww[j] * base[(size_t)j * KK];
    if (jh) half[tid & 127] = acc;
    __syncthreads();
    if (!jh) g_rlogp[(size_t)(jc * BB + b) * KK + k] = acc + half[tid];
}

// ---------------- knowledge: reduce partials + softmax + read ----------------
__global__ void __launch_bounds__(256) know_attend(const float* __restrict__ kn) {
    const int b = blockIdx.x, ic = blockIdx.y, tid = threadIdx.x;
    __shared__ float p[KK];
    __shared__ float red[256];
    float v0 = 0.f, v1 = 0.f;
#pragma unroll
    for (int jc = 0; jc < 4; jc++) {
        v0 += g_rlogp[(size_t)(jc * BB + b) * KK + tid];
        v1 += g_rlogp[(size_t)(jc * BB + b) * KK + 256 + tid];
    }
    red[tid] = fmaxf(v0, v1);
    __syncthreads();
    for (int st = 128; st >= 1; st >>= 1) {
        if (tid < st) red[tid] = fmaxf(red[tid], red[tid + st]);
        __syncthreads();
    }
    float mx = red[0];
    __syncthreads();
    float e0 = expf(v0 - mx), e1 = expf(v1 - mx);
    p[tid] = e0;
    p[tid + 256] = e1;
    red[tid] = e0 + e1;
    __syncthreads();
    for (int st = 128; st >= 1; st >>= 1) {
        if (tid < st) red[tid] += red[tid + st];
        __syncthreads();
    }
    float inv = 1.0f / red[0];
    __syncthreads();
    const int warp = tid >> 5, lane = tid & 31;
    const float4* p4 = (const float4*)p;
#pragma unroll
    for (int ii = 0; ii < 16; ii++) {
        int i = ic * 128 + warp * 16 + ii;
        const float4* row = (const float4*)(kn + (size_t)(b * DI + i) * KK);
        float acc = 0.f;
#pragma unroll
        for (int t2 = 0; t2 < 4; t2++) {
            float4 f = row[lane + 32 * t2];
            float4 q = p4[lane + 32 * t2];
            acc += f.x * q.x + f.y * q.y + f.z * q.z + f.w * q.w;
        }
#pragma unroll
        for (int o = 16; o; o >>= 1) acc += __shfl_xor_sync(0xffffffffu, acc, o);
        if (lane == 0) g_read[b * DI + i] = acc * inv;
    }
}

// ---------------- reduce new_memory partials + bias ----------------
__global__ void reduce_mem(const float* __restrict__ wmb, float* __restrict__ dst,
                           float* __restrict__ dst2) {
    int i = blockIdx.x * 256 + threadIdx.x;
    int n = i >> 10, m = i & 1023;
    float v = wmb[m];
#pragma unroll
    for (int z = 0; z < 8; z++) v += g_partA[(size_t)(z * BB + n) * DI + m];
    dst[i] = v;
    if (dst2) dst2[i] = v;
}

// ---------------- host orchestration ----------------
extern "C" void kernel_launch(void* const* d_in, const int* in_sizes, int n_in,
                              void* d_out, int out_size) {
    const float* ctx      = (const float*)d_in[0];
    const float* question = (const float*)d_in[1];
    const float* kn       = (const float*)d_in[2];
    const float* cinit    = (const float*)d_in[3];
    const float* pa_w     = (const float*)d_in[4];
    const float* pa_b     = (const float*)d_in[5];
    const float* cq_w     = (const float*)d_in[6];
    const float* cq_b     = (const float*)d_in[7];
    const float* ca_w     = (const float*)d_in[8];
    const float* rm_w     = (const float*)d_in[10];
    const float* rm_b     = (const float*)d_in[11];
    const float* ri_w     = (const float*)d_in[12];
    const float* ra_w     = (const float*)d_in[14];
    const float* wm_w     = (const float*)d_in[16];
    const float* wm_b     = (const float*)d_in[17];
    float* out = (float*)d_out;

    void* p;
    cudaGetSymbolAddress(&p, g_qpa);     float* qpa   = (float*)p;
    cudaGetSymbolAddress(&p, g_cq2);     float* cq2   = (float*)p;
    cudaGetSymbolAddress(&p, g_riwT);    float* riwT  = (float*)p;
    cudaGetSymbolAddress(&p, g_control); float* ctrl  = (float*)p;
    cudaGetSymbolAddress(&p, g_mem);     float* memb  = (float*)p;
    cudaGetSymbolAddress(&p, g_v);       float* vbuf  = (float*)p;
    cudaGetSymbolAddress(&p, g_read);    float* readb = (float*)p;
    cudaGetSymbolAddress(&p, g_partA);   float* partA = (float*)p;
    cudaGetSymbolAddress(&p, g_partB);   float* partB = (float*)p;

    // ---- precompute ----
    transpose_riw<<<dim3(64, 32), 256>>>(ri_w);
    // q_pa_all (+memory0): [12288 x 32] = pa_w @ question^T + pa_b
    sgemm_full<<<dim3(192, 1), 256>>>(pa_w, D2, question, D2,
                                      NSTEP * DI, D2, qpa, pa_b, 1, memb);
    // cq2: question-half of control-unit projection, N = 384
    sgemm_full<<<dim3(16, 12), 256>>>(cq_w + DI, D2, qpa, DI,
                                      DI, DI, cq2, cq_b, 0, nullptr);
    init_control<<<128, 256>>>(cinit);

    // ---- 12 recurrent steps ----
    for (int s = 0; s < NSTEP; s++) {
        GTask ta = { cq_w, D2, ctrl, ctrl, 1 << 30, DI, DI, 256, partA };
        GTask tb = { rm_w, DI, memb, memb, 1 << 30, DI, DI, 256, partB };
        sgemm_part<<<dim3(16, 2, 4), 256>>>(ta, tb);

        ctx_logits<<<dim3(BB, 4), 256>>>(ctx, ca_w, cq2 + (size_t)s * BB * DI);
        ctx_attend<<<dim3(BB, 4), 256>>>(ctx, ra_w);

        GTask tc = { riwT, DI, vbuf, vbuf, 1 << 30, DI, D2, 256, partA };
        sgemm_part<<<dim3(32, 1, 4), 256>>>(tc, tc);

        know_logits_part<<<dim3(BB, 4, 4), 256>>>(kn, rm_b);
        know_attend<<<dim3(BB, 8), 256>>>(kn);

        GTask td = { wm_w, D2, readb, memb, DI, DI, DI, 256, partA };
        sgemm_part<<<dim3(16, 1, 8), 256>>>(td, td);

        reduce_mem<<<128, 256>>>(wm_b, memb, (s == NSTEP - 1) ? out : nullptr);
    }
}

// round 4
// speedup vs baseline: 3.1938x; 1.5283x over previous
#include <cuda_runtime.h>

#define DI 1024
#define D2 2048
#define BB 32
#define SS 128
#define KK 512
#define NSTEP 12
#define NBLK 296
#define NTHR 256

// ---------------- static device scratch ----------------
__device__ __align__(16) float g_qpa[NSTEP * BB * DI];
__device__ __align__(16) float g_qpaP[4 * BB * NSTEP * DI];
__device__ __align__(16) float g_cq2[NSTEP * BB * DI];
__device__ __align__(16) float g_riwT[D2 * DI];
__device__ __align__(16) float g_control[BB * DI];
__device__ __align__(16) float g_mem[BB * DI];
__device__ __align__(16) float g_v[BB * DI];
__device__ __align__(16) float g_read[BB * DI];
__device__ __align__(16) float g_clog[BB * SS];
__device__ __align__(16) float g_rlogp[2 * BB * KK];
__device__ __align__(16) float g_partA[8 * BB * D2];
__device__ __align__(16) float g_partB[8 * BB * DI];
__device__ unsigned g_count = 0;
__device__ unsigned g_gen = 0;

// ---------------- grid-wide barrier ----------------
__device__ __forceinline__ void gsync() {
    __syncthreads();
    if (threadIdx.x == 0) {
        __threadfence();
        unsigned gen = *(volatile unsigned*)&g_gen;
        if (atomicAdd(&g_count, 1u) == NBLK - 1) {
            atomicExch(&g_count, 0u);
            __threadfence();
            atomicAdd(&g_gen, 1u);
        } else {
            while (*(volatile unsigned*)&g_gen == gen) __nanosleep(128);
        }
        __threadfence();
    }
    __syncthreads();
}

// ---------------- 64m x 32n GEMM tile over one k-chunk ----------------
__device__ __forceinline__ void gemm_tile(
    const float* __restrict__ A, int lda, int m0, int kbase, int kchunk,
    const float* __restrict__ act, int ldact, int kact,
    float* __restrict__ dst, int dstride, const float* __restrict__ bias,
    float* __restrict__ pool) {
    float* As = pool;          // [64][65]
    float* Bs = pool + 4160;   // [64][36]
    const int tid = threadIdx.x;
    const int tm = tid & 31;
    const int n0 = (tid >> 5) * 4;
    float acc[2][4] = {};
    for (int ks = 0; ks < kchunk; ks += 64) {
#pragma unroll
        for (int i = 0; i < 4; i++) {
            int idx = tid + 256 * i;
            int kg = idx & 15, m = idx >> 4;
            float4 av = *(const float4*)(A + (size_t)(m0 + m) * lda + kbase + ks + kg * 4);
            float* as = As + m * 65 + kg * 4;
            as[0] = av.x; as[1] = av.y; as[2] = av.z; as[3] = av.w;
        }
#pragma unroll
        for (int i = 0; i < 2; i++) {
            int n = (tid & 15) + 16 * i;
            int kg = tid >> 4;
            float4 bv = *(const float4*)(act + (size_t)n * ldact + kact + ks + kg * 4);
            Bs[(kg * 4 + 0) * 36 + n] = bv.x;
            Bs[(kg * 4 + 1) * 36 + n] = bv.y;
            Bs[(kg * 4 + 2) * 36 + n] = bv.z;
            Bs[(kg * 4 + 3) * 36 + n] = bv.w;
        }
        __syncthreads();
#pragma unroll
        for (int k = 0; k < 64; k++) {
            float4 bv = *(const float4*)(Bs + k * 36 + n0);
            float a0 = As[tm * 65 + k], a1 = As[(tm + 32) * 65 + k];
            acc[0][0] += a0 * bv.x; acc[0][1] += a0 * bv.y;
            acc[0][2] += a0 * bv.z; acc[0][3] += a0 * bv.w;
            acc[1][0] += a1 * bv.x; acc[1][1] += a1 * bv.y;
            acc[1][2] += a1 * bv.z; acc[1][3] += a1 * bv.w;
        }
        __syncthreads();
    }
#pragma unroll
    for (int r = 0; r < 2; r++) {
        int m = m0 + tm + 32 * r;
        float bs = bias ? bias[m] : 0.0f;
#pragma unroll
        for (int c = 0; c < 4; c++)
            dst[(size_t)(n0 + c) * dstride + m] = acc[r][c] + bs;
    }
}

// ---------------- one persistent kernel for the whole network ----------------
__global__ void __launch_bounds__(NTHR, 2) mac_persistent(
    const float* __restrict__ ctx, const float* __restrict__ question,
    const float* __restrict__ kn, const float* __restrict__ cinit,
    const float* __restrict__ pa_w, const float* __restrict__ pa_b,
    const float* __restrict__ cq_w, const float* __restrict__ cq_b,
    const float* __restrict__ caw, const float* __restrict__ rm_w,
    const float* __restrict__ rm_b, const float* __restrict__ ri_w,
    const float* __restrict__ raw, const float* __restrict__ wm_w,
    const float* __restrict__ wm_b, float* __restrict__ out) {
    __shared__ __align__(16) float pool[6464];  // 25.9 KB
    const int bid = blockIdx.x;
    const int tid = threadIdx.x;

    // ===== Phase 0a: qpa partial GEMM + ri_w transpose + control init =====
    for (int t = bid; t < 768; t += NBLK) {
        int mt = t % 192, z = t / 192;
        gemm_tile(pa_w, D2, mt * 64, z * 512, 512, question, D2, z * 512,
                  g_qpaP + (size_t)z * BB * (NSTEP * DI), NSTEP * DI, nullptr, pool);
    }
    {
        int tx = tid & 31, ty = tid >> 5;  // ty 0..7
        for (int t = bid; t < 2048; t += NBLK) {
            int jt = t & 63, it = t >> 6;
            int j0 = jt * 32, i0 = it * 32;
            __syncthreads();
#pragma unroll
            for (int r = 0; r < 32; r += 8)
                pool[(ty + r) * 33 + tx] = ri_w[(size_t)(i0 + ty + r) * D2 + j0 + tx];
            __syncthreads();
#pragma unroll
            for (int r = 0; r < 32; r += 8)
                g_riwT[(size_t)(j0 + ty + r) * DI + i0 + tx] = pool[tx * 33 + ty + r];
        }
    }
    for (int i = bid * NTHR + tid; i < BB * DI; i += NBLK * NTHR) g_control[i] = cinit[0];
    gsync();

    // ===== Phase 0b: qpa reduce (+bias, scatter to [s][b][d], memory0) =====
    for (int idx = bid * NTHR + tid; idx < BB * NSTEP * DI; idx += NBLK * NTHR) {
        int n = idx / (NSTEP * DI);
        int m = idx - n * (NSTEP * DI);
        float v = pa_b[m];
#pragma unroll
        for (int z = 0; z < 4; z++) v += g_qpaP[(size_t)(z * BB + n) * (NSTEP * DI) + m];
        int s0 = m >> 10, d = m & 1023;
        g_qpa[(size_t)(s0 * BB + n) * DI + d] = v;
        if (s0 == 0) g_mem[n * DI + d] = v;
    }
    gsync();

    // ===== Phase 0c: cq2 = qpa @ cq_w[:,D:]^T + cq_b  (192 tasks) =====
    if (bid < 192) {
        int mt = bid & 15, nb = bid >> 4;
        gemm_tile(cq_w + DI, D2, mt * 64, 0, DI, g_qpa + (size_t)nb * BB * DI, DI, 0,
                  g_cq2 + (size_t)nb * BB * DI, DI, cq_b, pool);
    }
    gsync();

    // ===== 12 recurrent steps =====
    for (int s = 0; s < NSTEP; s++) {
        // ---- P1: cq control-half (ta) + mem_p (tb) split-k partials ----
        if (bid < 256) {
            int t = bid;
            if (t < 128) {
                int mt = t & 15, z = t >> 4;
                gemm_tile(cq_w, D2, mt * 64, z * 128, 128, g_control, DI, z * 128,
                          g_partA + (size_t)z * BB * DI, DI, nullptr, pool);
            } else {
                int q = t - 128;
                int mt = q & 15, z = q >> 4;
                gemm_tile(rm_w, DI, mt * 64, z * 128, 128, g_mem, DI, z * 128,
                          g_partB + (size_t)z * BB * DI, DI, nullptr, pool);
            }
        }
        gsync();

        // ---- P2: context logits ----
        if (bid < 256) {
            int b = bid >> 3, sc = bid & 7;
            float* w = pool;  // [1024]
            const float* cq2s = g_cq2 + ((size_t)s * BB + b) * DI;
            for (int d = tid; d < DI; d += NTHR) {
                float v = cq2s[d];
#pragma unroll
                for (int z = 0; z < 8; z++) v += g_partA[(size_t)(z * BB + b) * DI + d];
                w[d] = v * caw[d];
            }
            __syncthreads();
            int warp = tid >> 5, lane = tid & 31;
            const float4* w4 = (const float4*)w;
#pragma unroll
            for (int ri = 0; ri < 2; ri++) {
                int srow = sc * 16 + warp * 2 + ri;
                const float4* crow = (const float4*)(ctx + (size_t)(b * SS + srow) * DI);
                float acc = 0.f;
#pragma unroll
                for (int t2 = 0; t2 < 8; t2++) {
                    float4 f = crow[lane + 32 * t2];
                    float4 g = w4[lane + 32 * t2];
                    acc += f.x * g.x + f.y * g.y + f.z * g.z + f.w * g.w;
                }
#pragma unroll
                for (int o = 16; o; o >>= 1) acc += __shfl_xor_sync(0xffffffffu, acc, o);
                if (lane == 0) g_clog[b * SS + srow] = acc;
            }
            __syncthreads();
        }
        gsync();

        // ---- P3: context softmax + weighted sum -> control, v ----
        if (bid < 256) {
            int b = bid >> 3, dc = bid & 7;
            float* ps = pool;          // [128]
            float* red = pool + 128;   // [128]
            float* comb = pool + 256;  // [128]
            if (tid < SS) { float l = g_clog[b * SS + tid]; ps[tid] = l; red[tid] = l; }
            __syncthreads();
            for (int st = 64; st >= 1; st >>= 1) {
                if (tid < st) red[tid] = fmaxf(red[tid], red[tid + st]);
                __syncthreads();
            }
            float mx = red[0];
            __syncthreads();
            if (tid < SS) { float e = __expf(ps[tid] - mx); ps[tid] = e; red[tid] = e; }
            __syncthreads();
            for (int st = 64; st >= 1; st >>= 1) {
                if (tid < st) red[tid] += red[tid + st];
                __syncthreads();
            }
            float inv = 1.0f / red[0];
            __syncthreads();
            int th = tid & 127, sh = tid >> 7;
            int d = dc * 128 + th;
            const float* base = ctx + (size_t)b * SS * DI + (size_t)sh * 64 * DI + d;
            const float* pw = ps + sh * 64;
            float acc = 0.f;
#pragma unroll 16
            for (int s2 = 0; s2 < 64; s2++) acc += pw[s2] * base[(size_t)s2 * DI];
            if (sh) comb[th] = acc;
            __syncthreads();
            if (!sh) {
                float rv = (acc + comb[th]) * inv;
                g_control[b * DI + d] = rv;
                g_v[b * DI + d] = rv * raw[d];
            }
            __syncthreads();
        }
        gsync();

        // ---- P4: u = v @ riwT^T  (M=2048, split-k 8) ----
        if (bid < 256) {
            int mt = bid & 31, z = bid >> 5;
            gemm_tile(g_riwT, DI, mt * 64, z * 128, 128, g_v, DI, z * 128,
                      g_partA + (size_t)z * BB * D2, D2, nullptr, pool);
        }
        gsync();

        // ---- P5: knowledge logits (partial over j halves) ----
        if (bid < 256) {
            int b = bid >> 3, kc = (bid >> 1) & 3, jc = bid & 1;
            int j0 = jc * 512;
            float* w2 = pool;         // [512]
            float* half = pool + 512; // [128]
            for (int jj = tid; jj < 512; jj += NTHR) {
                int j = j0 + jj;
                float mp = rm_b[j], u1 = 0.f, u2 = 0.f;
#pragma unroll
                for (int z = 0; z < 8; z++) {
                    mp += g_partB[(size_t)(z * BB + b) * DI + j];
                    u1 += g_partA[(size_t)(z * BB + b) * D2 + j];
                    u2 += g_partA[(size_t)(z * BB + b) * D2 + DI + j];
                }
                w2[jj] = mp * u1 + u2;
            }
            __syncthreads();
            int k = kc * 128 + (tid & 127);
            int jh = tid >> 7;
            const float* base = kn + (size_t)b * DI * KK + (size_t)(j0 + jh * 256) * KK + k;
            const float* ww = w2 + jh * 256;
            float acc = 0.f;
#pragma unroll 8
            for (int j = 0; j < 256; j++) acc += ww[j] * base[(size_t)j * KK];
            if (jh) half[tid & 127] = acc;
            __syncthreads();
            if (!jh) g_rlogp[(size_t)(jc * BB + b) * KK + k] = acc + half[tid];
            __syncthreads();
        }
        gsync();

        // ---- P6: knowledge softmax + read ----
        if (bid < 256) {
            int b = bid >> 3, ic = bid & 7;
            float* ps = pool;          // [512]
            float* red = pool + 512;   // [256]
            float v0 = g_rlogp[(size_t)b * KK + tid] + g_rlogp[(size_t)(BB + b) * KK + tid];
            float v1 = g_rlogp[(size_t)b * KK + 256 + tid] +
                       g_rlogp[(size_t)(BB + b) * KK + 256 + tid];
            red[tid] = fmaxf(v0, v1);
            __syncthreads();
            for (int st = 128; st >= 1; st >>= 1) {
                if (tid < st) red[tid] = fmaxf(red[tid], red[tid + st]);
                __syncthreads();
            }
            float mx = red[0];
            __syncthreads();
            float e0 = __expf(v0 - mx), e1 = __expf(v1 - mx);
            ps[tid] = e0;
            ps[tid + 256] = e1;
            red[tid] = e0 + e1;
            __syncthreads();
            for (int st = 128; st >= 1; st >>= 1) {
                if (tid < st) red[tid] += red[tid + st];
                __syncthreads();
            }
            float inv = 1.0f / red[0];
            __syncthreads();
            int warp = tid >> 5, lane = tid & 31;
            const float4* p4 = (const float4*)ps;
#pragma unroll
            for (int ii = 0; ii < 16; ii++) {
                int i = ic * 128 + warp * 16 + ii;
                const float4* row = (const float4*)(kn + (size_t)(b * DI + i) * KK);
                float acc = 0.f;
#pragma unroll
                for (int t2 = 0; t2 < 4; t2++) {
                    float4 f = row[lane + 32 * t2];
                    float4 q = p4[lane + 32 * t2];
                    acc += f.x * q.x + f.y * q.y + f.z * q.z + f.w * q.w;
                }
#pragma unroll
                for (int o = 16; o; o >>= 1) acc += __shfl_xor_sync(0xffffffffu, acc, o);
                if (lane == 0) g_read[b * DI + i] = acc * inv;
            }
            __syncthreads();
        }
        gsync();

        // ---- P7: new_memory = concat(read, memory) @ wm_w^T (split-k 16) ----
        if (bid < 256) {
            int mt = bid & 15, z = bid >> 4;
            const float* act = (z < 8) ? g_read : g_mem;
            int kact = (z < 8) ? z * 128 : (z - 8) * 128;
            gemm_tile(wm_w, D2, mt * 64, z * 128, 128, act, DI, kact,
                      g_partA + (size_t)z * BB * DI, DI, nullptr, pool);
        }
        gsync();

        // ---- P8: reduce new_memory partials ----
        {
            int i = bid * NTHR + tid;
            if (i < BB * DI) {
                int m = i & (DI - 1);
                int n = i >> 10;
                float vsum = wm_b[m];
#pragma unroll
                for (int z = 0; z < 16; z++)
                    vsum += g_partA[(size_t)(z * BB + n) * DI + m];
                g_mem[i] = vsum;
                if (s == NSTEP - 1) out[i] = vsum;
            }
        }
        gsync();
    }
}

// ---------------- host ----------------
extern "C" void kernel_launch(void* const* d_in, const int* in_sizes, int n_in,
                              void* d_out, int out_size) {
    const float* ctx      = (const float*)d_in[0];
    const float* question = (const float*)d_in[1];
    const float* kn       = (const float*)d_in[2];
    const float* cinit    = (const float*)d_in[3];
    const float* pa_w     = (const float*)d_in[4];
    const float* pa_b     = (const float*)d_in[5];
    const float* cq_w     = (const float*)d_in[6];
    const float* cq_b     = (const float*)d_in[7];
    const float* ca_w     = (const float*)d_in[8];
    const float* rm_w     = (const float*)d_in[10];
    const float* rm_b     = (const float*)d_in[11];
    const float* ri_w     = (const float*)d_in[12];
    const float* ra_w     = (const float*)d_in[14];
    const float* wm_w     = (const float*)d_in[16];
    const float* wm_b     = (const float*)d_in[17];
    float* out = (float*)d_out;

    mac_persistent<<<NBLK, NTHR>>>(ctx, question, kn, cinit, pa_w, pa_b,
                                   cq_w, cq_b, ca_w, rm_w, rm_b, ri_w,
                                   ra_w, wm_w, wm_b, out);
}

// round 5
// speedup vs baseline: 3.2473x; 1.0167x over previous
#include <cuda_runtime.h>

#define DI 1024
#define D2 2048
#define BB 32
#define SS 128
#define KK 512
#define NSTEP 12
#define NBLK 296
#define NTHR 256

// ---------------- static device scratch ----------------
__device__ __align__(16) float g_qpa[NSTEP * BB * DI];
__device__ __align__(16) float g_qpaP[4 * BB * NSTEP * DI];
__device__ __align__(16) float g_cq2[NSTEP * BB * DI];
__device__ __align__(16) float g_riwT[D2 * DI];
__device__ __align__(16) float g_control[BB * DI];
__device__ __align__(16) float g_mem[BB * DI];
__device__ __align__(16) float g_v[BB * DI];
__device__ __align__(16) float g_read[BB * DI];
__device__ __align__(16) float g_clog[BB * SS];
__device__ __align__(16) float g_rlogp[2 * BB * KK];
__device__ __align__(16) float g_partA[8 * BB * D2];
__device__ __align__(16) float g_partB[8 * BB * DI];
__device__ unsigned g_count = 0;
__device__ unsigned g_gen = 0;

// ---------------- grid-wide barrier ----------------
__device__ __forceinline__ void gsync() {
    __syncthreads();
    if (threadIdx.x == 0) {
        __threadfence();
        unsigned gen = *(volatile unsigned*)&g_gen;
        if (atomicAdd(&g_count, 1u) == NBLK - 1) {
            atomicExch(&g_count, 0u);
            __threadfence();
            atomicAdd(&g_gen, 1u);
        } else {
            while (*(volatile unsigned*)&g_gen == gen) __nanosleep(128);
        }
        __threadfence();
    }
    __syncthreads();
}

// ---------------- 64m x 32n GEMM tile over one k-chunk ----------------
__device__ __forceinline__ void gemm_tile(
    const float* __restrict__ A, int lda, int m0, int kbase, int kchunk,
    const float* __restrict__ act, int ldact, int kact,
    float* __restrict__ dst, int dstride, const float* __restrict__ bias,
    float* __restrict__ pool) {
    float* As = pool;          // [64][65]
    float* Bs = pool + 4160;   // [64][36]
    const int tid = threadIdx.x;
    const int tm = tid & 31;
    const int n0 = (tid >> 5) * 4;
    float acc[2][4] = {};
    for (int ks = 0; ks < kchunk; ks += 64) {
#pragma unroll
        for (int i = 0; i < 4; i++) {
            int idx = tid + 256 * i;
            int kg = idx & 15, m = idx >> 4;
            float4 av = *(const float4*)(A + (size_t)(m0 + m) * lda + kbase + ks + kg * 4);
            float* as = As + m * 65 + kg * 4;
            as[0] = av.x; as[1] = av.y; as[2] = av.z; as[3] = av.w;
        }
#pragma unroll
        for (int i = 0; i < 2; i++) {
            int n = (tid & 15) + 16 * i;
            int kg = tid >> 4;
            float4 bv = *(const float4*)(act + (size_t)n * ldact + kact + ks + kg * 4);
            Bs[(kg * 4 + 0) * 36 + n] = bv.x;
            Bs[(kg * 4 + 1) * 36 + n] = bv.y;
            Bs[(kg * 4 + 2) * 36 + n] = bv.z;
            Bs[(kg * 4 + 3) * 36 + n] = bv.w;
        }
        __syncthreads();
#pragma unroll
        for (int k = 0; k < 64; k++) {
            float4 bv = *(const float4*)(Bs + k * 36 + n0);
            float a0 = As[tm * 65 + k], a1 = As[(tm + 32) * 65 + k];
            acc[0][0] += a0 * bv.x; acc[0][1] += a0 * bv.y;
            acc[0][2] += a0 * bv.z; acc[0][3] += a0 * bv.w;
            acc[1][0] += a1 * bv.x; acc[1][1] += a1 * bv.y;
            acc[1][2] += a1 * bv.z; acc[1][3] += a1 * bv.w;
        }
        __syncthreads();
    }
#pragma unroll
    for (int r = 0; r < 2; r++) {
        int m = m0 + tm + 32 * r;
        float bs = bias ? bias[m] : 0.0f;
#pragma unroll
        for (int c = 0; c < 4; c++)
            dst[(size_t)(n0 + c) * dstride + m] = acc[r][c] + bs;
    }
}

// ---------------- one persistent kernel for the whole network ----------------
__global__ void __launch_bounds__(NTHR, 2) mac_persistent(
    const float* __restrict__ ctx, const float* __restrict__ question,
    const float* __restrict__ kn, const float* __restrict__ cinit,
    const float* __restrict__ pa_w, const float* __restrict__ pa_b,
    const float* __restrict__ cq_w, const float* __restrict__ cq_b,
    const float* __restrict__ caw, const float* __restrict__ rm_w,
    const float* __restrict__ rm_b, const float* __restrict__ ri_w,
    const float* __restrict__ raw, const float* __restrict__ wm_w,
    const float* __restrict__ wm_b, float* __restrict__ out) {
    __shared__ __align__(16) float pool[6464];  // 25.9 KB
    const int bid = blockIdx.x;
    const int tid = threadIdx.x;

    // ===== Phase 0a: qpa partial GEMM + ri_w transpose + control init =====
    for (int t = bid; t < 768; t += NBLK) {
        int mt = t % 192, z = t / 192;
        gemm_tile(pa_w, D2, mt * 64, z * 512, 512, question, D2, z * 512,
                  g_qpaP + (size_t)z * BB * (NSTEP * DI), NSTEP * DI, nullptr, pool);
    }
    {
        int tx = tid & 31, ty = tid >> 5;  // ty 0..7
        for (int t = bid; t < 2048; t += NBLK) {
            int jt = t & 63, it = t >> 6;
            int j0 = jt * 32, i0 = it * 32;
            __syncthreads();
#pragma unroll
            for (int r = 0; r < 32; r += 8)
                pool[(ty + r) * 33 + tx] = ri_w[(size_t)(i0 + ty + r) * D2 + j0 + tx];
            __syncthreads();
#pragma unroll
            for (int r = 0; r < 32; r += 8)
                g_riwT[(size_t)(j0 + ty + r) * DI + i0 + tx] = pool[tx * 33 + ty + r];
        }
    }
    for (int i = bid * NTHR + tid; i < BB * DI; i += NBLK * NTHR) g_control[i] = cinit[0];
    gsync();

    // ===== Phase 0b: qpa reduce (+bias, scatter to [s][b][d], memory0) =====
    for (int idx = bid * NTHR + tid; idx < BB * NSTEP * DI; idx += NBLK * NTHR) {
        int n = idx / (NSTEP * DI);
        int m = idx - n * (NSTEP * DI);
        float v = pa_b[m];
#pragma unroll
        for (int z = 0; z < 4; z++) v += g_qpaP[(size_t)(z * BB + n) * (NSTEP * DI) + m];
        int s0 = m >> 10, d = m & 1023;
        g_qpa[(size_t)(s0 * BB + n) * DI + d] = v;
        if (s0 == 0) g_mem[n * DI + d] = v;
    }
    gsync();

    // ===== Phase 0c: cq2 = qpa @ cq_w[:,D:]^T + cq_b  (192 tasks) =====
    if (bid < 192) {
        int mt = bid & 15, nb = bid >> 4;
        gemm_tile(cq_w + DI, D2, mt * 64, 0, DI, g_qpa + (size_t)nb * BB * DI, DI, 0,
                  g_cq2 + (size_t)nb * BB * DI, DI, cq_b, pool);
    }
    gsync();

    // ===== 12 recurrent steps =====
    for (int s = 0; s < NSTEP; s++) {
        // ---- P1: cq control-half (ta) + mem_p (tb) split-k partials ----
        if (bid < 256) {
            int t = bid;
            if (t < 128) {
                int mt = t & 15, z = t >> 4;
                gemm_tile(cq_w, D2, mt * 64, z * 128, 128, g_control, DI, z * 128,
                          g_partA + (size_t)z * BB * DI, DI, nullptr, pool);
            } else {
                int q = t - 128;
                int mt = q & 15, z = q >> 4;
                gemm_tile(rm_w, DI, mt * 64, z * 128, 128, g_mem, DI, z * 128,
                          g_partB + (size_t)z * BB * DI, DI, nullptr, pool);
            }
        }
        gsync();

        // ---- P2: context logits ----
        if (bid < 256) {
            int b = bid >> 3, sc = bid & 7;
            float* w = pool;  // [1024]
            const float* cq2s = g_cq2 + ((size_t)s * BB + b) * DI;
            for (int d = tid; d < DI; d += NTHR) {
                float v = cq2s[d];
#pragma unroll
                for (int z = 0; z < 8; z++) v += g_partA[(size_t)(z * BB + b) * DI + d];
                w[d] = v * caw[d];
            }
            __syncthreads();
            int warp = tid >> 5, lane = tid & 31;
            const float4* w4 = (const float4*)w;
#pragma unroll
            for (int ri = 0; ri < 2; ri++) {
                int srow = sc * 16 + warp * 2 + ri;
                const float4* crow = (const float4*)(ctx + (size_t)(b * SS + srow) * DI);
                float acc = 0.f;
#pragma unroll
                for (int t2 = 0; t2 < 8; t2++) {
                    float4 f = crow[lane + 32 * t2];
                    float4 g = w4[lane + 32 * t2];
                    acc += f.x * g.x + f.y * g.y + f.z * g.z + f.w * g.w;
                }
#pragma unroll
                for (int o = 16; o; o >>= 1) acc += __shfl_xor_sync(0xffffffffu, acc, o);
                if (lane == 0) g_clog[b * SS + srow] = acc;
            }
            __syncthreads();
        }
        gsync();

        // ---- P3: context softmax + weighted sum -> control, v ----
        if (bid < 256) {
            int b = bid >> 3, dc = bid & 7;
            float* ps = pool;          // [128]
            float* red = pool + 128;   // [128]
            float* comb = pool + 256;  // [128]
            if (tid < SS) { float l = g_clog[b * SS + tid]; ps[tid] = l; red[tid] = l; }
            __syncthreads();
            for (int st = 64; st >= 1; st >>= 1) {
                if (tid < st) red[tid] = fmaxf(red[tid], red[tid + st]);
                __syncthreads();
            }
            float mx = red[0];
            __syncthreads();
            if (tid < SS) { float e = __expf(ps[tid] - mx); ps[tid] = e; red[tid] = e; }
            __syncthreads();
            for (int st = 64; st >= 1; st >>= 1) {
                if (tid < st) red[tid] += red[tid + st];
                __syncthreads();
            }
            float inv = 1.0f / red[0];
            __syncthreads();
            int th = tid & 127, sh = tid >> 7;
            int d = dc * 128 + th;
            const float* base = ctx + (size_t)b * SS * DI + (size_t)sh * 64 * DI + d;
            const float* pw = ps + sh * 64;
            float acc = 0.f;
#pragma unroll 16
            for (int s2 = 0; s2 < 64; s2++) acc += pw[s2] * base[(size_t)s2 * DI];
            if (sh) comb[th] = acc;
            __syncthreads();
            if (!sh) {
                float rv = (acc + comb[th]) * inv;
                g_control[b * DI + d] = rv;
                g_v[b * DI + d] = rv * raw[d];
            }
            __syncthreads();
        }
        gsync();

        // ---- P4: u = v @ riwT^T  (M=2048, split-k 8) ----
        if (bid < 256) {
            int mt = bid & 31, z = bid >> 5;
            gemm_tile(g_riwT, DI, mt * 64, z * 128, 128, g_v, DI, z * 128,
                      g_partA + (size_t)z * BB * D2, D2, nullptr, pool);
        }
        gsync();

        // ---- P5: knowledge logits (partial over j halves) ----
        if (bid < 256) {
            int b = bid >> 3, kc = (bid >> 1) & 3, jc = bid & 1;
            int j0 = jc * 512;
            float* w2 = pool;         // [512]
            float* half = pool + 512; // [128]
            for (int jj = tid; jj < 512; jj += NTHR) {
                int j = j0 + jj;
                float mp = rm_b[j], u1 = 0.f, u2 = 0.f;
#pragma unroll
                for (int z = 0; z < 8; z++) {
                    mp += g_partB[(size_t)(z * BB + b) * DI + j];
                    u1 += g_partA[(size_t)(z * BB + b) * D2 + j];
                    u2 += g_partA[(size_t)(z * BB + b) * D2 + DI + j];
                }
                w2[jj] = mp * u1 + u2;
            }
            __syncthreads();
            int k = kc * 128 + (tid & 127);
            int jh = tid >> 7;
            const float* base = kn + (size_t)b * DI * KK + (size_t)(j0 + jh * 256) * KK + k;
            const float* ww = w2 + jh * 256;
            float acc = 0.f;
#pragma unroll 8
            for (int j = 0; j < 256; j++) acc += ww[j] * base[(size_t)j * KK];
            if (jh) half[tid & 127] = acc;
            __syncthreads();
            if (!jh) g_rlogp[(size_t)(jc * BB + b) * KK + k] = acc + half[tid];
            __syncthreads();
        }
        gsync();

        // ---- P6: knowledge softmax + read ----
        if (bid < 256) {
            int b = bid >> 3, ic = bid & 7;
            float* ps = pool;          // [512]
            float* red = pool + 512;   // [256]
            float v0 = g_rlogp[(size_t)b * KK + tid] + g_rlogp[(size_t)(BB + b) * KK + tid];
            float v1 = g_rlogp[(size_t)b * KK + 256 + tid] +
                       g_rlogp[(size_t)(BB + b) * KK + 256 + tid];
            red[tid] = fmaxf(v0, v1);
            __syncthreads();
            for (int st = 128; st >= 1; st >>= 1) {
                if (tid < st) red[tid] = fmaxf(red[tid], red[tid + st]);
                __syncthreads();
            }
            float mx = red[0];
            __syncthreads();
            float e0 = __expf(v0 - mx), e1 = __expf(v1 - mx);
            ps[tid] = e0;
            ps[tid + 256] = e1;
            red[tid] = e0 + e1;
            __syncthreads();
            for (int st = 128; st >= 1; st >>= 1) {
                if (tid < st) red[tid] += red[tid + st];
                __syncthreads();
            }
            float inv = 1.0f / red[0];
            __syncthreads();
            int warp = tid >> 5, lane = tid & 31;
            const float4* p4 = (const float4*)ps;
#pragma unroll
            for (int ii = 0; ii < 16; ii++) {
                int i = ic * 128 + warp * 16 + ii;
                const float4* row = (const float4*)(kn + (size_t)(b * DI + i) * KK);
                float acc = 0.f;
#pragma unroll
                for (int t2 = 0; t2 < 4; t2++) {
                    float4 f = row[lane + 32 * t2];
                    float4 q = p4[lane + 32 * t2];
                    acc += f.x * q.x + f.y * q.y + f.z * q.z + f.w * q.w;
                }
#pragma unroll
                for (int o = 16; o; o >>= 1) acc += __shfl_xor_sync(0xffffffffu, acc, o);
                if (lane == 0) g_read[b * DI + i] = acc * inv;
            }
            __syncthreads();
        }
        gsync();

        // ---- P7: new_memory = concat(read, memory) @ wm_w^T (split-k 16) ----
        if (bid < 256) {
            int mt = bid & 15, z = bid >> 4;
            const float* act = (z < 8) ? g_read : g_mem;
            int kact = (z < 8) ? z * 128 : (z - 8) * 128;
            gemm_tile(wm_w, D2, mt * 64, z * 128, 128, act, DI, kact,
                      g_partA + (size_t)z * BB * DI, DI, nullptr, pool);
        }
        gsync();

        // ---- P8: reduce new_memory partials ----
        {
            int i = bid * NTHR + tid;
            if (i < BB * DI) {
                int m = i & (DI - 1);
                int n = i >> 10;
                float vsum = wm_b[m];
#pragma unroll
                for (int z = 0; z < 16; z++)
                    vsum += g_partA[(size_t)(z * BB + n) * DI + m];
                g_mem[i] = vsum;
                if (s == NSTEP - 1) out[i] = vsum;
            }
        }
        gsync();
    }
}

// ---------------- host ----------------
extern "C" void kernel_launch(void* const* d_in, const int* in_sizes, int n_in,
                              void* d_out, int out_size) {
    const float* ctx      = (const float*)d_in[0];
    const float* question = (const float*)d_in[1];
    const float* kn       = (const float*)d_in[2];
    const float* cinit    = (const float*)d_in[3];
    const float* pa_w     = (const float*)d_in[4];
    const float* pa_b     = (const float*)d_in[5];
    const float* cq_w     = (const float*)d_in[6];
    const float* cq_b     = (const float*)d_in[7];
    const float* ca_w     = (const float*)d_in[8];
    const float* rm_w     = (const float*)d_in[10];
    const float* rm_b     = (const float*)d_in[11];
    const float* ri_w     = (const float*)d_in[12];
    const float* ra_w     = (const float*)d_in[14];
    const float* wm_w     = (const float*)d_in[16];
    const float* wm_b     = (const float*)d_in[17];
    float* out = (float*)d_out;

    mac_persistent<<<NBLK, NTHR>>>(ctx, question, kn, cinit, pa_w, pa_b,
                                   cq_w, cq_b, ca_w, rm_w, rm_b, ri_w,
                                   ra_w, wm_w, wm_b, out);
}